// round 5
// baseline (speedup 1.0000x reference)
#include <cuda_runtime.h>
#include <cstddef>
#include <cstdint>

#define Bsz   1024
#define DF    2048
#define DIM   128
#define CC    8192
#define PP    8
#define NNq   4
#define NC    (NNq * CC)            // 32768
#define PC    (PP * CC)             // 65536
#define SIMW  (Bsz + PP + NNq * (CC - 1))  // 33796
#define SPLITK 16
#define STAGES 3

static constexpr size_t OFF_SIM  = 0;
static constexpr size_t OFF_LAB  = (size_t)Bsz * SIMW;
static constexpr size_t OFF_LQ   = OFF_LAB + (size_t)Bsz * SIMW;
static constexpr size_t OFF_LK   = OFF_LQ + (size_t)Bsz * CC;
static constexpr size_t OFF_NQ2  = OFF_LK + (size_t)Bsz * CC;
static constexpr size_t OFF_PQ2  = OFF_NQ2 + (size_t)DIM * NC;
static constexpr size_t OFF_NPTR = OFF_PQ2 + (size_t)DIM * PC;
static constexpr size_t OFF_PPTR = OFF_NPTR + CC;

// ---------------- device scratch ------------------------------------------
__device__ float g_Hq[(size_t)Bsz * DF];
__device__ float g_Hk[(size_t)Bsz * DF];
__device__ float g_HqR[(size_t)Bsz * DF];
__device__ float g_HkR[(size_t)Bsz * DF];
__device__ float g_midqR[(size_t)Bsz * DF];
__device__ float g_midkR[(size_t)Bsz * DF];
__device__ float g_W1T[(size_t)DF * DF];
__device__ float g_WlinT[(size_t)CC * DF];
__device__ float g_W2T[(size_t)DIM * DF];
__device__ float g_negT[(size_t)NC * DIM];
__device__ float g_scq[DF], g_shq[DF], g_sck[DF], g_shk[DF];
__device__ float g_featq[(size_t)Bsz * DIM];
__device__ float g_featk[(size_t)Bsz * DIM];
__device__ float g_featqR[(size_t)Bsz * DIM];
__device__ float g_featkR[(size_t)Bsz * DIM];
__device__ float g_fpart[(size_t)2 * SPLITK * Bsz * DIM];
__device__ int   g_rank[Bsz];
__device__ int   g_cntb[Bsz];

// ---------------- helpers --------------------------------------------------
__device__ __forceinline__ unsigned f2tf(float x) {
    unsigned u;
    asm("cvt.rna.tf32.f32 %0, %1;" : "=r"(u) : "f"(x));
    return u;
}
__device__ __forceinline__ float rna(float x) { return __uint_as_float(f2tf(x)); }

// k-permutation within 8-groups: logical t stored at (t&3)*2 + (t>>2)
__device__ __host__ __forceinline__ int prm8(int t) { return ((t & 3) << 1) + (t >> 2); }
__device__ __forceinline__ int prm(int idx) { return (idx & ~7) | prm8(idx & 7); }

__device__ __forceinline__ void mma_tf32(float c[4], const unsigned a[4],
                                         const unsigned b[2]) {
    asm volatile(
        "mma.sync.aligned.m16n8k8.row.col.f32.tf32.tf32.f32 "
        "{%0,%1,%2,%3}, {%4,%5,%6,%7}, {%8,%9}, {%0,%1,%2,%3};"
        : "+f"(c[0]), "+f"(c[1]), "+f"(c[2]), "+f"(c[3])
        : "r"(a[0]), "r"(a[1]), "r"(a[2]), "r"(a[3]), "r"(b[0]), "r"(b[1]));
}

__device__ __forceinline__ void cpa16(uint32_t saddr, const float* g) {
    asm volatile("cp.async.cg.shared.global [%0], [%1], 16;\n" :: "r"(saddr), "l"(g));
}
#define CP_COMMIT() asm volatile("cp.async.commit_group;\n" ::: "memory")
#define CP_WAIT1()  asm volatile("cp.async.wait_group 1;\n" ::: "memory")

// ---------------- TF32 mma.sync GEMM, 3-stage cp.async --------------------
// CTA tile 128 x TN (TN = 128 or 256), BK = 32, 256 threads.
// Warps: 2 along M (64 rows) x 4 along N (TN/4 cols each).
// A [M][K'], Bt [N][K'] in gmem: RNA-rounded, K pre-permuted within 8-groups.
// Smem: XOR-swizzled 16B chunks (chunk' = u ^ ((row&3)<<1)); fragment reads
// are float2 (k, k+4 pairs), conflict-free.
// MODE 0: +bias; z selects (A0,C0)/(A1,C1)
// MODE 2: split-K partial: z = qk*SPLITK + sk; C = C0 + z*Bsz*DIM
// MODE 3: plain
// MODE 4: neg scatter epilogue skipping labels[m]'s NNq columns
template <int MODE, int TN>
__global__ void __launch_bounds__(256, TN == 256 ? 1 : 2) mm_k(
    const float* __restrict__ A0, const float* __restrict__ A1,
    const float* __restrict__ Bt, const float* __restrict__ bias,
    float* __restrict__ C0, float* __restrict__ C1,
    int K, int ldc, const int* __restrict__ labels)
{
    constexpr int NT = TN / 32;           // nt count per warp (8 or 4)
    constexpr int TILEF = (128 + TN) * 32; // floats per stage
    extern __shared__ float smem[];

    const int tid   = threadIdx.x;
    const int lane  = tid & 31;
    const int warp  = tid >> 5;
    const int g     = lane >> 2;
    const int tig   = lane & 3;
    const int wm    = (warp & 1) * 64;
    const int wn    = (warp >> 1) * (TN / 4);
    const int mBase = blockIdx.y * 128;
    const int nBase = blockIdx.x * TN;

    int kBeg = 0, kEnd = K;
    const float* A;
    float* Cc;
    if (MODE == 2) {
        int qk = blockIdx.z >> 4;
        int sk = blockIdx.z & 15;
        kBeg = sk * (K / SPLITK);
        kEnd = kBeg + K / SPLITK;
        A  = qk ? A1 : A0;
        Cc = C0 + (size_t)blockIdx.z * ((size_t)Bsz * DIM);
    } else {
        A  = blockIdx.z ? A1 : A0;
        Cc = blockIdx.z ? C1 : C0;
    }

    // staging lambda: copy one BK=32 slab of A (128 rows) + B (TN rows)
    auto stage_load = [&](int s, int k0) {
        float* base = smem + s * TILEF;
        uint32_t sA = (uint32_t)__cvta_generic_to_shared(base);
        uint32_t sB = (uint32_t)__cvta_generic_to_shared(base + 128 * 32);
        {
            int r = tid >> 1, cb = (tid & 1) * 4;
            const float* src = A + (size_t)(mBase + r) * K + k0;
            #pragma unroll
            for (int i = 0; i < 4; i++) {
                int u = cb + i, su = u ^ ((r & 3) << 1);
                cpa16(sA + (uint32_t)(r * 128 + su * 16), src + u * 4);
            }
        }
        if (TN == 256) {
            int r = tid;
            const float* src = Bt + (size_t)(nBase + r) * K + k0;
            #pragma unroll
            for (int u = 0; u < 8; u++) {
                int su = u ^ ((r & 3) << 1);
                cpa16(sB + (uint32_t)(r * 128 + su * 16), src + u * 4);
            }
        } else {
            int r = tid >> 1, cb = (tid & 1) * 4;
            const float* src = Bt + (size_t)(nBase + r) * K + k0;
            #pragma unroll
            for (int i = 0; i < 4; i++) {
                int u = cb + i, su = u ^ ((r & 3) << 1);
                cpa16(sB + (uint32_t)(r * 128 + su * 16), src + u * 4);
            }
        }
    };

    float acc[4][NT][4] = {};

    const int nIter = (kEnd - kBeg) / 32;
    stage_load(0, kBeg);
    CP_COMMIT();
    stage_load(1, kBeg + 32);
    CP_COMMIT();

    for (int it = 0; it < nIter; ++it) {
        CP_WAIT1();
        __syncthreads();
        if (it + 2 < nIter) stage_load((it + 2) % STAGES, kBeg + (it + 2) * 32);
        CP_COMMIT();

        const float* sb = smem + (it % STAGES) * TILEF;
        const float2* A2 = (const float2*)sb;
        const float2* B2 = (const float2*)(sb + 128 * 32);
        #pragma unroll
        for (int kb = 0; kb < 4; kb++) {
            unsigned af[4][4], bf[NT][2];
            #pragma unroll
            for (int mt = 0; mt < 4; mt++) {
                int r0 = wm + mt * 16 + g;
                int xo = (kb * 4 + tig) ^ ((r0 & 3) << 2);
                float2 f0 = A2[r0 * 16 + xo];
                float2 f1 = A2[(r0 + 8) * 16 + xo];
                af[mt][0] = __float_as_uint(f0.x);
                af[mt][2] = __float_as_uint(f0.y);
                af[mt][1] = __float_as_uint(f1.x);
                af[mt][3] = __float_as_uint(f1.y);
            }
            #pragma unroll
            for (int nt = 0; nt < NT; nt++) {
                int nc = wn + nt * 8 + g;
                float2 fb = B2[nc * 16 + ((kb * 4 + tig) ^ ((nc & 3) << 2))];
                bf[nt][0] = __float_as_uint(fb.x);
                bf[nt][1] = __float_as_uint(fb.y);
            }
            #pragma unroll
            for (int mt = 0; mt < 4; mt++)
                #pragma unroll
                for (int nt = 0; nt < NT; nt++)
                    mma_tf32(acc[mt][nt], af[mt], bf[nt]);
        }
    }
    __syncthreads();

    // ---- epilogue ----
    #pragma unroll
    for (int mt = 0; mt < 4; mt++) {
        int r0 = mBase + wm + mt * 16 + g;
        int r1 = r0 + 8;
        int la0 = 0, la1 = 0;
        if (MODE == 4) { la0 = labels[r0] * NNq; la1 = labels[r1] * NNq; }
        #pragma unroll
        for (int nt = 0; nt < NT; nt++) {
            int c = nBase + wn + nt * 8 + 2 * tig;
            const float* a4 = acc[mt][nt];
            if (MODE == 4) {
                int n0 = c, n1 = c + 1;
                if (n0 < la0)             Cc[(size_t)r0 * ldc + n0]       = a4[0];
                else if (n0 >= la0 + NNq) Cc[(size_t)r0 * ldc + n0 - NNq] = a4[0];
                if (n1 < la0)             Cc[(size_t)r0 * ldc + n1]       = a4[1];
                else if (n1 >= la0 + NNq) Cc[(size_t)r0 * ldc + n1 - NNq] = a4[1];
                if (n0 < la1)             Cc[(size_t)r1 * ldc + n0]       = a4[2];
                else if (n0 >= la1 + NNq) Cc[(size_t)r1 * ldc + n0 - NNq] = a4[2];
                if (n1 < la1)             Cc[(size_t)r1 * ldc + n1]       = a4[3];
                else if (n1 >= la1 + NNq) Cc[(size_t)r1 * ldc + n1 - NNq] = a4[3];
            } else {
                float bx = 0.f, by = 0.f;
                if (MODE == 0) { bx = bias[c]; by = bias[c + 1]; }
                float2 v0 = { a4[0] + bx, a4[1] + by };
                float2 v1 = { a4[2] + bx, a4[3] + by };
                *(float2*)(Cc + (size_t)r0 * ldc + c) = v0;
                *(float2*)(Cc + (size_t)r1 * ldc + c) = v1;
            }
        }
    }
}

// ---------------- prep: round + k-permute (8 floats / thread) --------------
__global__ void round_perm_k(const float* __restrict__ in0, const float* __restrict__ in1,
                             float* __restrict__ o0, float* __restrict__ o1, int n8)
{
    const float* in = blockIdx.z ? in1 : in0;
    float* o = blockIdx.z ? o1 : o0;
    int i = blockIdx.x * blockDim.x + threadIdx.x;
    if (i >= n8) return;
    float4 a = ((const float4*)in)[i * 2];
    float4 b = ((const float4*)in)[i * 2 + 1];
    float4 p0 = { rna(a.x), rna(b.x), rna(a.y), rna(b.y) };
    float4 p1 = { rna(a.z), rna(b.z), rna(a.w), rna(b.w) };
    ((float4*)o)[i * 2]     = p0;
    ((float4*)o)[i * 2 + 1] = p1;
}

// ---------------- prep: transpose + round + k-permute ----------------------
// in [R][C] -> out [C][R'], column (=orig row) permuted within 8-groups
__global__ void transpose_perm_k(const float* __restrict__ in, float* __restrict__ out,
                                 int R, int C)
{
    __shared__ float t[32][33];
    int cx = blockIdx.x * 32 + threadIdx.x;
    int ry = blockIdx.y * 32 + threadIdx.y;
    #pragma unroll
    for (int j = 0; j < 32; j += 8)
        t[threadIdx.y + j][threadIdx.x] = in[(size_t)(ry + j) * C + cx];
    __syncthreads();
    int cx2 = blockIdx.y * 32 + threadIdx.x;
    int ry2 = blockIdx.x * 32 + threadIdx.y;
    int cx2p = (cx2 & ~7) | prm8(cx2 & 7);
    #pragma unroll
    for (int j = 0; j < 32; j += 8)
        out[(size_t)(ry2 + j) * R + cx2p] = rna(t[threadIdx.x][threadIdx.y + j]);
}

// ---------------- BN stats -------------------------------------------------
__global__ void bn_stats_k(const float* __restrict__ Hq, const float* __restrict__ Hk,
                           const float* __restrict__ gamma, const float* __restrict__ beta,
                           float* __restrict__ scq, float* __restrict__ shq,
                           float* __restrict__ sck, float* __restrict__ shk)
{
    const float* H = blockIdx.z ? Hk : Hq;
    float* scale = blockIdx.z ? sck : scq;
    float* shift = blockIdx.z ? shk : shq;
    int f = blockIdx.x * 32 + threadIdx.x;
    float s = 0.f, ss = 0.f;
    for (int rr = threadIdx.y; rr < Bsz; rr += 32) {
        float v = H[(size_t)rr * DF + f];
        s += v; ss += v * v;
    }
    __shared__ float sh_s[32][33], sh_ss[32][33];
    sh_s[threadIdx.y][threadIdx.x]  = s;
    sh_ss[threadIdx.y][threadIdx.x] = ss;
    __syncthreads();
    if (threadIdx.y == 0) {
        #pragma unroll
        for (int y = 1; y < 32; y++) {
            s += sh_s[y][threadIdx.x]; ss += sh_ss[y][threadIdx.x];
        }
        float mu  = s * (1.f / Bsz);
        float var = ss * (1.f / Bsz) - mu * mu;
        float rst = rsqrtf(var + 1e-5f);
        float scv = rst * gamma[f];
        scale[f] = scv;
        shift[f] = beta[f] - mu * scv;
    }
}

// ---------------- BN apply + relu + round + k-permute ----------------------
__global__ void bnrelu_perm_k(const float* __restrict__ Hq, const float* __restrict__ Hk,
                              float* __restrict__ Rq, float* __restrict__ Rk)
{
    const float* H = blockIdx.z ? Hk : Hq;
    float* R = blockIdx.z ? Rk : Rq;
    const float* sc = blockIdx.z ? g_sck : g_scq;
    const float* sh = blockIdx.z ? g_shk : g_shq;
    int i = blockIdx.x * blockDim.x + threadIdx.x;   // 8-float group index
    int f = (i * 8) & (DF - 1);
    float4 a = ((const float4*)H)[i * 2];
    float4 b = ((const float4*)H)[i * 2 + 1];
    float4 sa = *(const float4*)(sc + f);
    float4 sb = *(const float4*)(sc + f + 4);
    float4 ha = *(const float4*)(sh + f);
    float4 hb = *(const float4*)(sh + f + 4);
    a.x = rna(fmaxf(fmaf(a.x, sa.x, ha.x), 0.f));
    a.y = rna(fmaxf(fmaf(a.y, sa.y, ha.y), 0.f));
    a.z = rna(fmaxf(fmaf(a.z, sa.z, ha.z), 0.f));
    a.w = rna(fmaxf(fmaf(a.w, sa.w, ha.w), 0.f));
    b.x = rna(fmaxf(fmaf(b.x, sb.x, hb.x), 0.f));
    b.y = rna(fmaxf(fmaf(b.y, sb.y, hb.y), 0.f));
    b.z = rna(fmaxf(fmaf(b.z, sb.z, hb.z), 0.f));
    b.w = rna(fmaxf(fmaf(b.w, sb.w, hb.w), 0.f));
    float4 p0 = { a.x, b.x, a.y, b.y };
    float4 p1 = { a.z, b.z, a.w, b.w };
    ((float4*)R)[i * 2]     = p0;
    ((float4*)R)[i * 2 + 1] = p1;
}

// ---------------- split-K reduce + bias + l2norm ---------------------------
__global__ void reduce_l2_k(const float* __restrict__ b2)
{
    int qk = blockIdx.y, b = blockIdx.x, d = threadIdx.x;  // d: 0..127
    const float* part = g_fpart + (size_t)qk * SPLITK * Bsz * DIM;
    float v = b2[d];
    #pragma unroll
    for (int s = 0; s < SPLITK; s++)
        v += part[(size_t)s * Bsz * DIM + (size_t)b * DIM + d];
    float ss = v * v;
    #pragma unroll
    for (int o = 16; o; o >>= 1) ss += __shfl_xor_sync(0xffffffffu, ss, o);
    __shared__ float ws[4];
    if ((d & 31) == 0) ws[d >> 5] = ss;
    __syncthreads();
    ss = ws[0] + ws[1] + ws[2] + ws[3];
    float inv = 1.f / fmaxf(sqrtf(ss), 1e-12f);
    float vn = v * inv;
    int dp = prm(d);
    if (qk) { g_featk[(size_t)b * DIM + d] = vn; g_featkR[(size_t)b * DIM + dp] = rna(vn); }
    else    { g_featq[(size_t)b * DIM + d] = vn; g_featqR[(size_t)b * DIM + dp] = rna(vn); }
}

// ---------------- pos_list --------------------------------------------------
__global__ void pos_k(const int* __restrict__ lq, const float* __restrict__ posq,
                      float* __restrict__ out)
{
    int b = blockIdx.x, tid = threadIdx.x;
    __shared__ float fr[DIM];
    if (tid < DIM) fr[tid] = g_featq[(size_t)b * DIM + tid];
    __syncthreads();
    int w = tid >> 5, lane = tid & 31;
    int col = lq[b] * PP + w;
    float s = 0.f;
    for (int d = lane; d < DIM; d += 32)
        s += fr[d] * posq[(size_t)d * PC + col];
    #pragma unroll
    for (int o = 16; o; o >>= 1) s += __shfl_down_sync(0xffffffffu, s, o);
    if (lane == 0) out[OFF_SIM + (size_t)b * SIMW + Bsz + w] = s;
}

// ---------------- labels_con fill ------------------------------------------
__global__ void labels_fill_k(const int* __restrict__ lq, const int* __restrict__ lk,
                              float* __restrict__ out)
{
    size_t i4 = (size_t)blockIdx.x * blockDim.x + threadIdx.x;
    const size_t total4 = (size_t)Bsz * (SIMW / 4);
    if (i4 >= total4) return;
    int row = (int)(i4 / (SIMW / 4));
    int c0  = (int)(i4 % (SIMW / 4)) * 4;
    float4 v;
    if (c0 + 4 <= Bsz) {
        int l = lq[row];
        v.x = (lk[c0 + 0] == l) ? 1.f : 0.f;
        v.y = (lk[c0 + 1] == l) ? 1.f : 0.f;
        v.z = (lk[c0 + 2] == l) ? 1.f : 0.f;
        v.w = (lk[c0 + 3] == l) ? 1.f : 0.f;
    } else if (c0 >= Bsz && c0 + 4 <= Bsz + PP) {
        v.x = v.y = v.z = v.w = 1.f;
    } else {
        v.x = v.y = v.z = v.w = 0.f;
    }
    *(float4*)(out + OFF_LAB + (size_t)row * SIMW + c0) = v;
}

// ---------------- occurrence rank + per-row class count --------------------
__global__ void rank_k(const int* __restrict__ lk)
{
    __shared__ int sl[Bsz];
    int b = threadIdx.x;
    sl[b] = lk[b];
    __syncthreads();
    int lab = sl[b];
    int r = 0, c = 0;
    for (int j = 0; j < Bsz; j++) {
        int e = (sl[j] == lab);
        c += e;
        r += e & (j < b);
    }
    g_rank[b] = r;
    g_cntb[b] = c;
}

// ---------------- ptr outputs ----------------------------------------------
__global__ void ptr_k(const int* __restrict__ lk, const int* __restrict__ nptr,
                      const int* __restrict__ pptr, float* __restrict__ out)
{
    __shared__ int sl[Bsz];
    for (int i = threadIdx.x; i < Bsz; i += blockDim.x) sl[i] = lk[i];
    __syncthreads();
    int c = blockIdx.x * blockDim.x + threadIdx.x;
    int cnt = 0;
    for (int j = 0; j < Bsz; j++) cnt += (sl[j] == c);
    out[OFF_NPTR + c] = (float)((nptr[c] + cnt) % NNq);
    out[OFF_PPTR + c] = (float)((pptr[c] + cnt) % PP);
}

// ---------------- queue overwrite ------------------------------------------
__global__ void queue_update_k(const int* __restrict__ lk, const int* __restrict__ nptr,
                               const int* __restrict__ pptr, float* __restrict__ out)
{
    int b = blockIdx.x;
    int d = threadIdx.x;   // 128
    int lab = lk[b];
    int r = g_rank[b];
    int c = g_cntb[b];
    float v = g_featk[(size_t)b * DIM + d];
    if (r >= c - NNq) {
        int slot = (nptr[lab] + r) % NNq;
        out[OFF_NQ2 + (size_t)d * NC + lab * NNq + slot] = v;
    }
    if (r >= c - PP) {
        int slot = (pptr[lab] + r) % PP;
        out[OFF_PQ2 + (size_t)d * PC + lab * PP + slot] = v;
    }
}

// ---------------- host launcher --------------------------------------------
static float* symf(const void* sym) {
    void* p = nullptr;
    cudaGetSymbolAddress(&p, sym);
    return (float*)p;
}

extern "C" void kernel_launch(void* const* d_in, const int* in_sizes, int n_in,
                              void* d_out, int out_size)
{
    (void)in_sizes; (void)n_in; (void)out_size;
    const float* midq  = (const float*)d_in[0];
    const float* midk  = (const float*)d_in[1];
    const int*   lq    = (const int*)d_in[2];
    const int*   lk    = (const int*)d_in[3];
    const float* W1    = (const float*)d_in[4];
    const float* b1    = (const float*)d_in[5];
    const float* gamma = (const float*)d_in[6];
    const float* beta  = (const float*)d_in[7];
    const float* W2    = (const float*)d_in[8];
    const float* b2    = (const float*)d_in[9];
    const float* Wlin  = (const float*)d_in[10];
    const float* blin  = (const float*)d_in[11];
    const float* negq  = (const float*)d_in[12];
    const float* posq  = (const float*)d_in[13];
    const int*   nptr  = (const int*)d_in[14];
    const int*   pptr  = (const int*)d_in[15];
    float* out = (float*)d_out;

    float* Hq    = symf(g_Hq);
    float* Hk    = symf(g_Hk);
    float* HqR   = symf(g_HqR);
    float* HkR   = symf(g_HkR);
    float* midqR = symf(g_midqR);
    float* midkR = symf(g_midkR);
    float* W1T   = symf(g_W1T);
    float* WlinT = symf(g_WlinT);
    float* W2T   = symf(g_W2T);
    float* negT  = symf(g_negT);
    float* scq = symf(g_scq); float* shq = symf(g_shq);
    float* sck = symf(g_sck); float* shk = symf(g_shk);
    float* fqR = symf(g_featqR);
    float* fkR = symf(g_featkR);
    float* fpart = symf(g_fpart);

    const int SM256 = STAGES * (128 + 256) * 32 * 4;   // 147456
    const int SM128 = STAGES * (128 + 128) * 32 * 4;   // 98304
    cudaFuncSetAttribute(mm_k<0, 256>, cudaFuncAttributeMaxDynamicSharedMemorySize, SM256);
    cudaFuncSetAttribute(mm_k<4, 256>, cudaFuncAttributeMaxDynamicSharedMemorySize, SM256);
    cudaFuncSetAttribute(mm_k<2, 128>, cudaFuncAttributeMaxDynamicSharedMemorySize, SM128);
    cudaFuncSetAttribute(mm_k<3, 128>, cudaFuncAttributeMaxDynamicSharedMemorySize, SM128);

    // queues copied to output (queue_update overwrites survivors)
    cudaMemcpyAsync(out + OFF_NQ2, negq, sizeof(float) * (size_t)DIM * NC,
                    cudaMemcpyDeviceToDevice);
    cudaMemcpyAsync(out + OFF_PQ2, posq, sizeof(float) * (size_t)DIM * PC,
                    cudaMemcpyDeviceToDevice);

    // ---- prep: round+permute activations; transpose+round+permute weights ----
    round_perm_k<<<dim3(Bsz * DF / 8 / 256, 1, 2), 256>>>(
        midq, midk, midqR, midkR, Bsz * DF / 8);
    transpose_perm_k<<<dim3(CC / 32, DF / 32), dim3(32, 8)>>>(Wlin, WlinT, DF, CC);
    transpose_perm_k<<<dim3(DF / 32, DF / 32), dim3(32, 8)>>>(W1, W1T, DF, DF);
    transpose_perm_k<<<dim3(DIM / 32, DF / 32), dim3(32, 8)>>>(W2, W2T, DF, DIM);
    transpose_perm_k<<<dim3(NC / 32, DIM / 32), dim3(32, 8)>>>(negq, negT, DIM, NC);

    // ---- logits: mid @ Wlin + blin ----
    mm_k<0, 256><<<dim3(CC / 256, Bsz / 128, 2), 256, SM256>>>(
        midqR, midkR, WlinT, blin, out + OFF_LQ, out + OFF_LK, DF, CC, nullptr);

    // ---- H = mid @ W1 + b1 ----
    mm_k<0, 256><<<dim3(DF / 256, Bsz / 128, 2), 256, SM256>>>(
        midqR, midkR, W1T, b1, Hq, Hk, DF, DF, nullptr);

    // ---- BN stats + apply(relu)+round+permute ----
    bn_stats_k<<<dim3(DF / 32, 1, 2), dim3(32, 32)>>>(
        Hq, Hk, gamma, beta, scq, shq, sck, shk);
    bnrelu_perm_k<<<dim3(Bsz * DF / 8 / 256, 1, 2), 256>>>(Hq, Hk, HqR, HkR);

    // ---- feat partials = relu(BN(H)) @ W2 (split-K 16, q/k via z) ----
    mm_k<2, 128><<<dim3(1, Bsz / 128, 2 * SPLITK), 256, SM128>>>(
        HqR, HkR, W2T, nullptr, fpart, nullptr, DF, DIM, nullptr);

    // ---- reduce + bias + l2norm ----
    reduce_l2_k<<<dim3(Bsz, 2), DIM>>>(b2);

    // ---- sim_batch = feat_q @ feat_k^T ----
    mm_k<3, 128><<<dim3(Bsz / 128, Bsz / 128, 1), 256, SM128>>>(
        fqR, nullptr, fkR, nullptr, out + OFF_SIM, nullptr, DIM, SIMW, nullptr);

    // ---- pos_list ----
    pos_k<<<Bsz, 256>>>(lq, posq, out);

    // ---- neg gathered ----
    mm_k<4, 256><<<dim3(NC / 256, Bsz / 128, 1), 256, SM256>>>(
        fqR, nullptr, negT, nullptr, out + OFF_SIM + Bsz + PP, nullptr,
        DIM, SIMW, lq);

    // ---- labels_con ----
    {
        size_t total4 = (size_t)Bsz * (SIMW / 4);
        int blocks = (int)((total4 + 255) / 256);
        labels_fill_k<<<blocks, 256>>>(lq, lk, out);
    }

    // ---- queue update ----
    rank_k<<<1, Bsz>>>(lk);
    ptr_k<<<CC / 256, 256>>>(lk, nptr, pptr, out);
    queue_update_k<<<Bsz, DIM>>>(lk, nptr, pptr, out);
}

// round 6
// speedup vs baseline: 1.2676x; 1.2676x over previous
#include <cuda_runtime.h>
#include <cstddef>
#include <cstdint>

#define Bsz   1024
#define DF    2048
#define DIM   128
#define CC    8192
#define PP    8
#define NNq   4
#define NC    (NNq * CC)            // 32768
#define PC    (PP * CC)             // 65536
#define SIMW  (Bsz + PP + NNq * (CC - 1))  // 33796
#define SPLITK 16
#define STAGES 3

static constexpr size_t OFF_SIM  = 0;
static constexpr size_t OFF_LAB  = (size_t)Bsz * SIMW;
static constexpr size_t OFF_LQ   = OFF_LAB + (size_t)Bsz * SIMW;
static constexpr size_t OFF_LK   = OFF_LQ + (size_t)Bsz * CC;
static constexpr size_t OFF_NQ2  = OFF_LK + (size_t)Bsz * CC;
static constexpr size_t OFF_PQ2  = OFF_NQ2 + (size_t)DIM * NC;
static constexpr size_t OFF_NPTR = OFF_PQ2 + (size_t)DIM * PC;
static constexpr size_t OFF_PPTR = OFF_NPTR + CC;

// ---------------- device scratch ------------------------------------------
__device__ float g_Hq[(size_t)Bsz * DF];
__device__ float g_Hk[(size_t)Bsz * DF];
__device__ float g_HqR[(size_t)Bsz * DF];
__device__ float g_HkR[(size_t)Bsz * DF];
__device__ float g_midqR[(size_t)Bsz * DF];
__device__ float g_midkR[(size_t)Bsz * DF];
__device__ float g_W1T[(size_t)DF * DF];
__device__ float g_WlinT[(size_t)CC * DF];
__device__ float g_W2T[(size_t)DIM * DF];
__device__ float g_negT[(size_t)NC * DIM];
__device__ float g_scq[DF], g_shq[DF], g_sck[DF], g_shk[DF];
__device__ float g_featq[(size_t)Bsz * DIM];
__device__ float g_featk[(size_t)Bsz * DIM];
__device__ float g_featqR[(size_t)Bsz * DIM];
__device__ float g_featkR[(size_t)Bsz * DIM];
__device__ float g_fpart[(size_t)2 * SPLITK * Bsz * DIM];
__device__ int   g_rank[Bsz];
__device__ int   g_cntb[Bsz];

// ---------------- helpers --------------------------------------------------
__device__ __forceinline__ unsigned f2tf(float x) {
    unsigned u;
    asm("cvt.rna.tf32.f32 %0, %1;" : "=r"(u) : "f"(x));
    return u;
}
__device__ __forceinline__ float rna(float x) { return __uint_as_float(f2tf(x)); }

// k-permutation within 8-groups: logical t stored at (t&3)*2 + (t>>2)
__device__ __host__ __forceinline__ int prm8(int t) { return ((t & 3) << 1) + (t >> 2); }
__device__ __forceinline__ int prm(int idx) { return (idx & ~7) | prm8(idx & 7); }

__device__ __forceinline__ void mma_tf32(float c[4], const unsigned a[4],
                                         const unsigned b[2]) {
    asm volatile(
        "mma.sync.aligned.m16n8k8.row.col.f32.tf32.tf32.f32 "
        "{%0,%1,%2,%3}, {%4,%5,%6,%7}, {%8,%9}, {%0,%1,%2,%3};"
        : "+f"(c[0]), "+f"(c[1]), "+f"(c[2]), "+f"(c[3])
        : "r"(a[0]), "r"(a[1]), "r"(a[2]), "r"(a[3]), "r"(b[0]), "r"(b[1]));
}

__device__ __forceinline__ void cpa16(uint32_t saddr, const float* g) {
    asm volatile("cp.async.cg.shared.global [%0], [%1], 16;\n" :: "r"(saddr), "l"(g));
}
#define CP_COMMIT() asm volatile("cp.async.commit_group;\n" ::: "memory")
#define CP_WAIT1()  asm volatile("cp.async.wait_group 1;\n" ::: "memory")

// ---------------- TF32 mma.sync GEMM, 3-stage cp.async --------------------
// CTA tile 128x128, BK=32, 256 threads (8 warps, warp tile 64x32).
// A [M][K'], Bt [N][K'] in gmem: RNA-rounded, K pre-permuted within 8-groups.
// Smem: XOR-swizzled 16B chunks (chunk' = u ^ ((row&3)<<1)); fragment reads
// are float2 (k,k+4 pairs), conflict-free; zero cvt in the mainloop.
// MODE 0: +bias; z selects (A0,C0)/(A1,C1)
// MODE 2: split-K partial: z = qk*SPLITK + sk; C = C0 + z*Bsz*DIM
// MODE 3: plain
// MODE 4: neg scatter epilogue skipping labels[m]'s NNq columns
template <int MODE>
__global__ void __launch_bounds__(256, 2) mm_k(
    const float* __restrict__ A0, const float* __restrict__ A1,
    const float* __restrict__ Bt, const float* __restrict__ bias,
    float* __restrict__ C0, float* __restrict__ C1,
    int K, int ldc, const int* __restrict__ labels)
{
    constexpr int TILEF = 256 * 32;       // floats per stage (A 128x32 + B 128x32)
    extern __shared__ float smem[];

    const int tid   = threadIdx.x;
    const int lane  = tid & 31;
    const int warp  = tid >> 5;
    const int g     = lane >> 2;
    const int tig   = lane & 3;
    const int wm    = (warp & 1) * 64;
    const int wn    = (warp >> 1) * 32;
    const int mBase = blockIdx.y * 128;
    const int nBase = blockIdx.x * 128;

    int kBeg = 0, kEnd = K;
    const float* A;
    float* Cc;
    if (MODE == 2) {
        int qk = blockIdx.z >> 4;
        int sk = blockIdx.z & 15;
        kBeg = sk * (K / SPLITK);
        kEnd = kBeg + K / SPLITK;
        A  = qk ? A1 : A0;
        Cc = C0 + (size_t)blockIdx.z * ((size_t)Bsz * DIM);
    } else {
        A  = blockIdx.z ? A1 : A0;
        Cc = blockIdx.z ? C1 : C0;
    }

    // staging: 256 threads, each copies 4x16B for A and 4x16B for B
    const int sr = tid >> 1;            // row 0..127
    const int scb = (tid & 1) * 4;      // chunk base 0 or 4
    auto stage_load = [&](int s, int k0) {
        float* base = smem + s * TILEF;
        uint32_t sA = (uint32_t)__cvta_generic_to_shared(base);
        uint32_t sB = sA + 128 * 32 * 4;
        const float* srcA = A  + (size_t)(mBase + sr) * K + k0;
        const float* srcB = Bt + (size_t)(nBase + sr) * K + k0;
        #pragma unroll
        for (int i = 0; i < 4; i++) {
            int u = scb + i, su = u ^ ((sr & 3) << 1);
            cpa16(sA + (uint32_t)(sr * 128 + su * 16), srcA + u * 4);
            cpa16(sB + (uint32_t)(sr * 128 + su * 16), srcB + u * 4);
        }
    };

    float acc[4][4][4] = {};

    const int nIter = (kEnd - kBeg) / 32;
    stage_load(0, kBeg);
    CP_COMMIT();
    stage_load(1, kBeg + 32);
    CP_COMMIT();

    for (int it = 0; it < nIter; ++it) {
        CP_WAIT1();
        __syncthreads();
        if (it + 2 < nIter) {
            stage_load((it + 2) % STAGES, kBeg + (it + 2) * 32);
        }
        CP_COMMIT();

        const float2* A2 = (const float2*)(smem + (it % STAGES) * TILEF);
        const float2* B2 = A2 + 128 * 16;
        #pragma unroll
        for (int kb = 0; kb < 4; kb++) {
            unsigned af[4][4], bf[4][2];
            #pragma unroll
            for (int mt = 0; mt < 4; mt++) {
                int r0 = wm + mt * 16 + g;
                int xo = (kb * 4 + tig) ^ ((r0 & 3) << 2);
                float2 f0 = A2[r0 * 16 + xo];
                float2 f1 = A2[(r0 + 8) * 16 + xo];
                af[mt][0] = __float_as_uint(f0.x);
                af[mt][2] = __float_as_uint(f0.y);
                af[mt][1] = __float_as_uint(f1.x);
                af[mt][3] = __float_as_uint(f1.y);
            }
            #pragma unroll
            for (int nt = 0; nt < 4; nt++) {
                int nc = wn + nt * 8 + g;
                float2 fb = B2[nc * 16 + ((kb * 4 + tig) ^ ((nc & 3) << 2))];
                bf[nt][0] = __float_as_uint(fb.x);
                bf[nt][1] = __float_as_uint(fb.y);
            }
            #pragma unroll
            for (int mt = 0; mt < 4; mt++)
                #pragma unroll
                for (int nt = 0; nt < 4; nt++)
                    mma_tf32(acc[mt][nt], af[mt], bf[nt]);
        }
        __syncthreads();
    }

    // ---- epilogue ----
    #pragma unroll
    for (int mt = 0; mt < 4; mt++) {
        int r0 = mBase + wm + mt * 16 + g;
        int r1 = r0 + 8;
        int la0 = 0, la1 = 0;
        if (MODE == 4) { la0 = labels[r0] * NNq; la1 = labels[r1] * NNq; }
        #pragma unroll
        for (int nt = 0; nt < 4; nt++) {
            int c = nBase + wn + nt * 8 + 2 * tig;
            const float* a4 = acc[mt][nt];
            if (MODE == 4) {
                int n0 = c, n1 = c + 1;
                if (n0 < la0)             Cc[(size_t)r0 * ldc + n0]       = a4[0];
                else if (n0 >= la0 + NNq) Cc[(size_t)r0 * ldc + n0 - NNq] = a4[0];
                if (n1 < la0)             Cc[(size_t)r0 * ldc + n1]       = a4[1];
                else if (n1 >= la0 + NNq) Cc[(size_t)r0 * ldc + n1 - NNq] = a4[1];
                if (n0 < la1)             Cc[(size_t)r1 * ldc + n0]       = a4[2];
                else if (n0 >= la1 + NNq) Cc[(size_t)r1 * ldc + n0 - NNq] = a4[2];
                if (n1 < la1)             Cc[(size_t)r1 * ldc + n1]       = a4[3];
                else if (n1 >= la1 + NNq) Cc[(size_t)r1 * ldc + n1 - NNq] = a4[3];
            } else {
                float bx = 0.f, by = 0.f;
                if (MODE == 0) { bx = bias[c]; by = bias[c + 1]; }
                float2 v0 = { a4[0] + bx, a4[1] + by };
                float2 v1 = { a4[2] + bx, a4[3] + by };
                *(float2*)(Cc + (size_t)r0 * ldc + c) = v0;
                *(float2*)(Cc + (size_t)r1 * ldc + c) = v1;
            }
        }
    }
}

// ---------------- prep: round + k-permute (8 floats / thread) --------------
__global__ void round_perm_k(const float* __restrict__ in0, const float* __restrict__ in1,
                             float* __restrict__ o0, float* __restrict__ o1, int n8)
{
    const float* in = blockIdx.z ? in1 : in0;
    float* o = blockIdx.z ? o1 : o0;
    int i = blockIdx.x * blockDim.x + threadIdx.x;
    if (i >= n8) return;
    float4 a = ((const float4*)in)[i * 2];
    float4 b = ((const float4*)in)[i * 2 + 1];
    float4 p0 = { rna(a.x), rna(b.x), rna(a.y), rna(b.y) };
    float4 p1 = { rna(a.z), rna(b.z), rna(a.w), rna(b.w) };
    ((float4*)o)[i * 2]     = p0;
    ((float4*)o)[i * 2 + 1] = p1;
}

// ---------------- prep: transpose + round + k-permute ----------------------
// in [R][C] -> out [C][R'], column (=orig row) permuted within 8-groups
__global__ void transpose_perm_k(const float* __restrict__ in, float* __restrict__ out,
                                 int R, int C)
{
    __shared__ float t[32][33];
    int cx = blockIdx.x * 32 + threadIdx.x;
    int ry = blockIdx.y * 32 + threadIdx.y;
    #pragma unroll
    for (int j = 0; j < 32; j += 8)
        t[threadIdx.y + j][threadIdx.x] = in[(size_t)(ry + j) * C + cx];
    __syncthreads();
    int cx2 = blockIdx.y * 32 + threadIdx.x;
    int ry2 = blockIdx.x * 32 + threadIdx.y;
    int cx2p = (cx2 & ~7) | prm8(cx2 & 7);
    #pragma unroll
    for (int j = 0; j < 32; j += 8)
        out[(size_t)(ry2 + j) * R + cx2p] = rna(t[threadIdx.x][threadIdx.y + j]);
}

// ---------------- BN stats -------------------------------------------------
__global__ void bn_stats_k(const float* __restrict__ Hq, const float* __restrict__ Hk,
                           const float* __restrict__ gamma, const float* __restrict__ beta,
                           float* __restrict__ scq, float* __restrict__ shq,
                           float* __restrict__ sck, float* __restrict__ shk)
{
    const float* H = blockIdx.z ? Hk : Hq;
    float* scale = blockIdx.z ? sck : scq;
    float* shift = blockIdx.z ? shk : shq;
    int f = blockIdx.x * 32 + threadIdx.x;
    float s = 0.f, ss = 0.f;
    for (int rr = threadIdx.y; rr < Bsz; rr += 32) {
        float v = H[(size_t)rr * DF + f];
        s += v; ss += v * v;
    }
    __shared__ float sh_s[32][33], sh_ss[32][33];
    sh_s[threadIdx.y][threadIdx.x]  = s;
    sh_ss[threadIdx.y][threadIdx.x] = ss;
    __syncthreads();
    if (threadIdx.y == 0) {
        #pragma unroll
        for (int y = 1; y < 32; y++) {
            s += sh_s[y][threadIdx.x]; ss += sh_ss[y][threadIdx.x];
        }
        float mu  = s * (1.f / Bsz);
        float var = ss * (1.f / Bsz) - mu * mu;
        float rst = rsqrtf(var + 1e-5f);
        float scv = rst * gamma[f];
        scale[f] = scv;
        shift[f] = beta[f] - mu * scv;
    }
}

// ---------------- BN apply + relu + round + k-permute ----------------------
__global__ void bnrelu_perm_k(const float* __restrict__ Hq, const float* __restrict__ Hk,
                              float* __restrict__ Rq, float* __restrict__ Rk)
{
    const float* H = blockIdx.z ? Hk : Hq;
    float* R = blockIdx.z ? Rk : Rq;
    const float* sc = blockIdx.z ? g_sck : g_scq;
    const float* sh = blockIdx.z ? g_shk : g_shq;
    int i = blockIdx.x * blockDim.x + threadIdx.x;   // 8-float group index
    int f = (i * 8) & (DF - 1);
    float4 a = ((const float4*)H)[i * 2];
    float4 b = ((const float4*)H)[i * 2 + 1];
    float4 sa = *(const float4*)(sc + f);
    float4 sb = *(const float4*)(sc + f + 4);
    float4 ha = *(const float4*)(sh + f);
    float4 hb = *(const float4*)(sh + f + 4);
    a.x = rna(fmaxf(fmaf(a.x, sa.x, ha.x), 0.f));
    a.y = rna(fmaxf(fmaf(a.y, sa.y, ha.y), 0.f));
    a.z = rna(fmaxf(fmaf(a.z, sa.z, ha.z), 0.f));
    a.w = rna(fmaxf(fmaf(a.w, sa.w, ha.w), 0.f));
    b.x = rna(fmaxf(fmaf(b.x, sb.x, hb.x), 0.f));
    b.y = rna(fmaxf(fmaf(b.y, sb.y, hb.y), 0.f));
    b.z = rna(fmaxf(fmaf(b.z, sb.z, hb.z), 0.f));
    b.w = rna(fmaxf(fmaf(b.w, sb.w, hb.w), 0.f));
    float4 p0 = { a.x, b.x, a.y, b.y };
    float4 p1 = { a.z, b.z, a.w, b.w };
    ((float4*)R)[i * 2]     = p0;
    ((float4*)R)[i * 2 + 1] = p1;
}

// ---------------- split-K reduce + bias + l2norm ---------------------------
__global__ void reduce_l2_k(const float* __restrict__ b2)
{
    int qk = blockIdx.y, b = blockIdx.x, d = threadIdx.x;  // d: 0..127
    const float* part = g_fpart + (size_t)qk * SPLITK * Bsz * DIM;
    float v = b2[d];
    #pragma unroll
    for (int s = 0; s < SPLITK; s++)
        v += part[(size_t)s * Bsz * DIM + (size_t)b * DIM + d];
    float ss = v * v;
    #pragma unroll
    for (int o = 16; o; o >>= 1) ss += __shfl_xor_sync(0xffffffffu, ss, o);
    __shared__ float ws[4];
    if ((d & 31) == 0) ws[d >> 5] = ss;
    __syncthreads();
    ss = ws[0] + ws[1] + ws[2] + ws[3];
    float inv = 1.f / fmaxf(sqrtf(ss), 1e-12f);
    float vn = v * inv;
    int dp = prm(d);
    if (qk) { g_featk[(size_t)b * DIM + d] = vn; g_featkR[(size_t)b * DIM + dp] = rna(vn); }
    else    { g_featq[(size_t)b * DIM + d] = vn; g_featqR[(size_t)b * DIM + dp] = rna(vn); }
}

// ---------------- pos_list --------------------------------------------------
__global__ void pos_k(const int* __restrict__ lq, const float* __restrict__ posq,
                      float* __restrict__ out)
{
    int b = blockIdx.x, tid = threadIdx.x;
    __shared__ float fr[DIM];
    if (tid < DIM) fr[tid] = g_featq[(size_t)b * DIM + tid];
    __syncthreads();
    int w = tid >> 5, lane = tid & 31;
    int col = lq[b] * PP + w;
    float s = 0.f;
    for (int d = lane; d < DIM; d += 32)
        s += fr[d] * posq[(size_t)d * PC + col];
    #pragma unroll
    for (int o = 16; o; o >>= 1) s += __shfl_down_sync(0xffffffffu, s, o);
    if (lane == 0) out[OFF_SIM + (size_t)b * SIMW + Bsz + w] = s;
}

// ---------------- labels_con fill ------------------------------------------
__global__ void labels_fill_k(const int* __restrict__ lq, const int* __restrict__ lk,
                              float* __restrict__ out)
{
    size_t i4 = (size_t)blockIdx.x * blockDim.x + threadIdx.x;
    const size_t total4 = (size_t)Bsz * (SIMW / 4);
    if (i4 >= total4) return;
    int row = (int)(i4 / (SIMW / 4));
    int c0  = (int)(i4 % (SIMW / 4)) * 4;
    float4 v;
    if (c0 + 4 <= Bsz) {
        int l = lq[row];
        v.x = (lk[c0 + 0] == l) ? 1.f : 0.f;
        v.y = (lk[c0 + 1] == l) ? 1.f : 0.f;
        v.z = (lk[c0 + 2] == l) ? 1.f : 0.f;
        v.w = (lk[c0 + 3] == l) ? 1.f : 0.f;
    } else if (c0 >= Bsz && c0 + 4 <= Bsz + PP) {
        v.x = v.y = v.z = v.w = 1.f;
    } else {
        v.x = v.y = v.z = v.w = 0.f;
    }
    *(float4*)(out + OFF_LAB + (size_t)row * SIMW + c0) = v;
}

// ---------------- occurrence rank + per-row class count --------------------
__global__ void rank_k(const int* __restrict__ lk)
{
    __shared__ int sl[Bsz];
    int b = threadIdx.x;
    sl[b] = lk[b];
    __syncthreads();
    int lab = sl[b];
    int r = 0, c = 0;
    for (int j = 0; j < Bsz; j++) {
        int e = (sl[j] == lab);
        c += e;
        r += e & (j < b);
    }
    g_rank[b] = r;
    g_cntb[b] = c;
}

// ---------------- ptr outputs ----------------------------------------------
__global__ void ptr_k(const int* __restrict__ lk, const int* __restrict__ nptr,
                      const int* __restrict__ pptr, float* __restrict__ out)
{
    __shared__ int sl[Bsz];
    for (int i = threadIdx.x; i < Bsz; i += blockDim.x) sl[i] = lk[i];
    __syncthreads();
    int c = blockIdx.x * blockDim.x + threadIdx.x;
    int cnt = 0;
    for (int j = 0; j < Bsz; j++) cnt += (sl[j] == c);
    out[OFF_NPTR + c] = (float)((nptr[c] + cnt) % NNq);
    out[OFF_PPTR + c] = (float)((pptr[c] + cnt) % PP);
}

// ---------------- queue overwrite ------------------------------------------
__global__ void queue_update_k(const int* __restrict__ lk, const int* __restrict__ nptr,
                               const int* __restrict__ pptr, float* __restrict__ out)
{
    int b = blockIdx.x;
    int d = threadIdx.x;   // 128
    int lab = lk[b];
    int r = g_rank[b];
    int c = g_cntb[b];
    float v = g_featk[(size_t)b * DIM + d];
    if (r >= c - NNq) {
        int slot = (nptr[lab] + r) % NNq;
        out[OFF_NQ2 + (size_t)d * NC + lab * NNq + slot] = v;
    }
    if (r >= c - PP) {
        int slot = (pptr[lab] + r) % PP;
        out[OFF_PQ2 + (size_t)d * PC + lab * PP + slot] = v;
    }
}

// ---------------- host launcher --------------------------------------------
static float* symf(const void* sym) {
    void* p = nullptr;
    cudaGetSymbolAddress(&p, sym);
    return (float*)p;
}

extern "C" void kernel_launch(void* const* d_in, const int* in_sizes, int n_in,
                              void* d_out, int out_size)
{
    (void)in_sizes; (void)n_in; (void)out_size;
    const float* midq  = (const float*)d_in[0];
    const float* midk  = (const float*)d_in[1];
    const int*   lq    = (const int*)d_in[2];
    const int*   lk    = (const int*)d_in[3];
    const float* W1    = (const float*)d_in[4];
    const float* b1    = (const float*)d_in[5];
    const float* gamma = (const float*)d_in[6];
    const float* beta  = (const float*)d_in[7];
    const float* W2    = (const float*)d_in[8];
    const float* b2    = (const float*)d_in[9];
    const float* Wlin  = (const float*)d_in[10];
    const float* blin  = (const float*)d_in[11];
    const float* negq  = (const float*)d_in[12];
    const float* posq  = (const float*)d_in[13];
    const int*   nptr  = (const int*)d_in[14];
    const int*   pptr  = (const int*)d_in[15];
    float* out = (float*)d_out;

    float* Hq    = symf(g_Hq);
    float* Hk    = symf(g_Hk);
    float* HqR   = symf(g_HqR);
    float* HkR   = symf(g_HkR);
    float* midqR = symf(g_midqR);
    float* midkR = symf(g_midkR);
    float* W1T   = symf(g_W1T);
    float* WlinT = symf(g_WlinT);
    float* W2T   = symf(g_W2T);
    float* negT  = symf(g_negT);
    float* scq = symf(g_scq); float* shq = symf(g_shq);
    float* sck = symf(g_sck); float* shk = symf(g_shk);
    float* fqR = symf(g_featqR);
    float* fkR = symf(g_featkR);
    float* fpart = symf(g_fpart);

    const int SMSZ = STAGES * 256 * 32 * 4;   // 98304
    cudaFuncSetAttribute(mm_k<0>, cudaFuncAttributeMaxDynamicSharedMemorySize, SMSZ);
    cudaFuncSetAttribute(mm_k<2>, cudaFuncAttributeMaxDynamicSharedMemorySize, SMSZ);
    cudaFuncSetAttribute(mm_k<3>, cudaFuncAttributeMaxDynamicSharedMemorySize, SMSZ);
    cudaFuncSetAttribute(mm_k<4>, cudaFuncAttributeMaxDynamicSharedMemorySize, SMSZ);

    // queues copied to output (queue_update overwrites survivors)
    cudaMemcpyAsync(out + OFF_NQ2, negq, sizeof(float) * (size_t)DIM * NC,
                    cudaMemcpyDeviceToDevice);
    cudaMemcpyAsync(out + OFF_PQ2, posq, sizeof(float) * (size_t)DIM * PC,
                    cudaMemcpyDeviceToDevice);

    // ---- prep: round+permute activations; transpose+round+permute weights ----
    round_perm_k<<<dim3(Bsz * DF / 8 / 256, 1, 2), 256>>>(
        midq, midk, midqR, midkR, Bsz * DF / 8);
    transpose_perm_k<<<dim3(CC / 32, DF / 32), dim3(32, 8)>>>(Wlin, WlinT, DF, CC);
    transpose_perm_k<<<dim3(DF / 32, DF / 32), dim3(32, 8)>>>(W1, W1T, DF, DF);
    transpose_perm_k<<<dim3(DIM / 32, DF / 32), dim3(32, 8)>>>(W2, W2T, DF, DIM);
    transpose_perm_k<<<dim3(NC / 32, DIM / 32), dim3(32, 8)>>>(negq, negT, DIM, NC);

    // ---- logits: mid @ Wlin + blin ----
    mm_k<0><<<dim3(CC / 128, Bsz / 128, 2), 256, SMSZ>>>(
        midqR, midkR, WlinT, blin, out + OFF_LQ, out + OFF_LK, DF, CC, nullptr);

    // ---- H = mid @ W1 + b1 ----
    mm_k<0><<<dim3(DF / 128, Bsz / 128, 2), 256, SMSZ>>>(
        midqR, midkR, W1T, b1, Hq, Hk, DF, DF, nullptr);

    // ---- BN stats + apply(relu)+round+permute ----
    bn_stats_k<<<dim3(DF / 32, 1, 2), dim3(32, 32)>>>(
        Hq, Hk, gamma, beta, scq, shq, sck, shk);
    bnrelu_perm_k<<<dim3(Bsz * DF / 8 / 256, 1, 2), 256>>>(Hq, Hk, HqR, HkR);

    // ---- feat partials = relu(BN(H)) @ W2 (split-K 16, q/k via z) ----
    mm_k<2><<<dim3(1, Bsz / 128, 2 * SPLITK), 256, SMSZ>>>(
        HqR, HkR, W2T, nullptr, fpart, nullptr, DF, DIM, nullptr);

    // ---- reduce + bias + l2norm ----
    reduce_l2_k<<<dim3(Bsz, 2), DIM>>>(b2);

    // ---- sim_batch = feat_q @ feat_k^T ----
    mm_k<3><<<dim3(Bsz / 128, Bsz / 128, 1), 256, SMSZ>>>(
        fqR, nullptr, fkR, nullptr, out + OFF_SIM, nullptr, DIM, SIMW, nullptr);

    // ---- pos_list ----
    pos_k<<<Bsz, 256>>>(lq, posq, out);

    // ---- neg gathered ----
    mm_k<4><<<dim3(NC / 128, Bsz / 128, 1), 256, SMSZ>>>(
        fqR, nullptr, negT, nullptr, out + OFF_SIM + Bsz + PP, nullptr,
        DIM, SIMW, lq);

    // ---- labels_con ----
    {
        size_t total4 = (size_t)Bsz * (SIMW / 4);
        int blocks = (int)((total4 + 255) / 256);
        labels_fill_k<<<blocks, 256>>>(lq, lk, out);
    }

    // ---- queue update ----
    rank_k<<<1, Bsz>>>(lk);
    ptr_k<<<CC / 256, 256>>>(lk, nptr, pptr, out);
    queue_update_k<<<Bsz, DIM>>>(lk, nptr, pptr, out);
}